// round 3
// baseline (speedup 1.0000x reference)
#include <cuda_runtime.h>
#include <math.h>

// EGNN layer collapsed to the diagonal (eye-mask kills off-diagonal edges).
// Per row r: t1 = silu(h@(We1a+We1b) + sqrt(EPS)*We1[2F] + be1)
//            t2 = silu(t1@We2 + be2)
//            att = sigmoid(t2.Wa + ba)        [warp-uniform scalar]
//            t3 = silu(bn1 + h@Wn1a + att*(t2@Wn1b))   <- att factored out
//            out = t3@Wn2 + bn2
// Two rows per warp (amortize weight loads, 2x ILP). Lane = neuron.
// S_h (=h@Wn1a) fused into layer-1 loop (reuses shfl(hv,f)).
// Att butterfly reduction overlaps with the S_t2 (=t2@Wn1b) accumulation.

#define SQRT_EPS 0.0031622776601683794f  // sqrt(1e-5)
#define FULL 0xffffffffu

__device__ __forceinline__ float silu_f(float v) {
    return __fdividef(v, 1.0f + __expf(-v));
}
__device__ __forceinline__ float sigmoid_f(float v) {
    return __fdividef(1.0f, 1.0f + __expf(-v));
}

__global__ void __launch_bounds__(256)
egnn_diag_kernel(const float* __restrict__ h,
                 const float* __restrict__ x,
                 const float* __restrict__ We1, const float* __restrict__ be1,
                 const float* __restrict__ We2, const float* __restrict__ be2,
                 const float* __restrict__ Wa,  const float* __restrict__ ba,
                 const float* __restrict__ Wn1, const float* __restrict__ bn1,
                 const float* __restrict__ Wn2, const float* __restrict__ bn2,
                 float* __restrict__ out, float* __restrict__ xout, int R)
{
    const int warp = (blockIdx.x * blockDim.x + threadIdx.x) >> 5;
    const int lane = threadIdx.x & 31;
    const int r0 = warp * 2;
    const int r1 = r0 + 1;
    if (r0 >= R) return;
    const bool has1 = (r1 < R);

    // ---- independent front-loaded work ----
    const float hv0 = h[r0 * 32 + lane];
    const float hv1 = has1 ? h[r1 * 32 + lane] : 0.f;

    if (lane < 3) {
        xout[r0 * 3 + lane] = x[r0 * 3 + lane];
        if (has1) xout[r1 * 3 + lane] = x[r1 * 3 + lane];
    }

    const float b1  = be1[lane] + SQRT_EPS * We1[64 * 32 + lane];
    const float b2  = be2[lane];
    const float wa  = Wa[lane];
    const float ba0 = ba[0];
    const float b3  = bn1[lane];
    const float b4  = bn2[lane];

    // critical-path weights into registers (loads overlap layer-1 compute)
    float we2r[32], wn2r[32];
    #pragma unroll
    for (int f = 0; f < 32; ++f) we2r[f] = We2[f * 32 + lane];
    #pragma unroll
    for (int f = 0; f < 32; ++f) wn2r[f] = Wn2[f * 32 + lane];

    // ---- layer 1 + S_h fused (reuse shfl(hv,f) for We1 and Wn1a) ----
    float a0_0 = b1, a1_0 = 0.f, a0_1 = b1, a1_1 = 0.f;
    float sh0a = 0.f, sh0b = 0.f, sh1a = 0.f, sh1b = 0.f;
    #pragma unroll
    for (int f = 0; f < 32; f += 2) {
        const float w1a = We1[(f + 0) * 32 + lane] + We1[(32 + f + 0) * 32 + lane];
        const float wna = Wn1[(f + 0) * 32 + lane];
        const float hf0a = __shfl_sync(FULL, hv0, f + 0);
        const float hf1a = __shfl_sync(FULL, hv1, f + 0);
        a0_0 += hf0a * w1a;  a0_1 += hf1a * w1a;
        sh0a += hf0a * wna;  sh1a += hf1a * wna;

        const float w1b = We1[(f + 1) * 32 + lane] + We1[(32 + f + 1) * 32 + lane];
        const float wnb = Wn1[(f + 1) * 32 + lane];
        const float hf0b = __shfl_sync(FULL, hv0, f + 1);
        const float hf1b = __shfl_sync(FULL, hv1, f + 1);
        a1_0 += hf0b * w1b;  a1_1 += hf1b * w1b;
        sh0b += hf0b * wnb;  sh1b += hf1b * wnb;
    }
    const float t1_0 = silu_f(a0_0 + a1_0);
    const float t1_1 = silu_f(a0_1 + a1_1);
    const float sh0 = sh0a + sh0b;
    const float sh1 = sh1a + sh1b;

    // ---- layer 2: t2 = silu(t1 @ We2 + be2), register weights ----
    a0_0 = b2; a1_0 = 0.f; a0_1 = b2; a1_1 = 0.f;
    #pragma unroll
    for (int f = 0; f < 32; f += 2) {
        a0_0 += __shfl_sync(FULL, t1_0, f + 0) * we2r[f + 0];
        a0_1 += __shfl_sync(FULL, t1_1, f + 0) * we2r[f + 0];
        a1_0 += __shfl_sync(FULL, t1_0, f + 1) * we2r[f + 1];
        a1_1 += __shfl_sync(FULL, t1_1, f + 1) * we2r[f + 1];
    }
    const float t2_0 = silu_f(a0_0 + a1_0);
    const float t2_1 = silu_f(a0_1 + a1_1);

    // ---- att reduction (butterfly) overlapped with S_t2 = t2 @ Wn1b ----
    float s0 = t2_0 * wa;
    float s1 = t2_1 * wa;
    float st0a = 0.f, st0b = 0.f, st1a = 0.f, st1b = 0.f;
    #pragma unroll
    for (int f = 0; f < 32; f += 2) {
        const float wba = Wn1[(32 + f + 0) * 32 + lane];
        const float wbb = Wn1[(32 + f + 1) * 32 + lane];
        st0a += __shfl_sync(FULL, t2_0, f + 0) * wba;
        st1a += __shfl_sync(FULL, t2_1, f + 0) * wba;
        st0b += __shfl_sync(FULL, t2_0, f + 1) * wbb;
        st1b += __shfl_sync(FULL, t2_1, f + 1) * wbb;
    }
    #pragma unroll
    for (int off = 16; off > 0; off >>= 1) {
        s0 += __shfl_xor_sync(FULL, s0, off);
        s1 += __shfl_xor_sync(FULL, s1, off);
    }
    const float att0 = sigmoid_f(s0 + ba0);
    const float att1 = sigmoid_f(s1 + ba0);

    // ---- layer 3 epilogue: t3 = silu(b3 + S_h + att * S_t2) ----
    const float t3_0 = silu_f(b3 + sh0 + att0 * (st0a + st0b));
    const float t3_1 = silu_f(b3 + sh1 + att1 * (st1a + st1b));

    // ---- layer 4: out = t3 @ Wn2 + bn2, register weights ----
    a0_0 = b4; a1_0 = 0.f; a0_1 = b4; a1_1 = 0.f;
    #pragma unroll
    for (int f = 0; f < 32; f += 2) {
        a0_0 += __shfl_sync(FULL, t3_0, f + 0) * wn2r[f + 0];
        a0_1 += __shfl_sync(FULL, t3_1, f + 0) * wn2r[f + 0];
        a1_0 += __shfl_sync(FULL, t3_0, f + 1) * wn2r[f + 1];
        a1_1 += __shfl_sync(FULL, t3_1, f + 1) * wn2r[f + 1];
    }

    out[r0 * 32 + lane] = a0_0 + a1_0;
    if (has1) out[r1 * 32 + lane] = a0_1 + a1_1;
}

extern "C" void kernel_launch(void* const* d_in, const int* in_sizes, int n_in,
                              void* d_out, int out_size)
{
    const float* h   = (const float*)d_in[0];
    const float* x   = (const float*)d_in[1];
    const float* We1 = (const float*)d_in[2];
    const float* be1 = (const float*)d_in[3];
    const float* We2 = (const float*)d_in[4];
    const float* be2 = (const float*)d_in[5];
    const float* Wa  = (const float*)d_in[6];
    const float* ba  = (const float*)d_in[7];
    const float* Wn1 = (const float*)d_in[8];
    const float* bn1 = (const float*)d_in[9];
    const float* Wn2 = (const float*)d_in[10];
    const float* bn2 = (const float*)d_in[11];

    const int R = in_sizes[0] / 32;          // B*N rows
    float* out  = (float*)d_out;             // [R, 32]
    float* xout = out + (size_t)R * 32;      // [R, 3] passthrough

    const int nwarps  = (R + 1) / 2;         // 2 rows per warp
    const int threads = 256;                 // 8 warps/block
    const int blocks  = (nwarps * 32 + threads - 1) / threads;  // 128 for R=2048
    egnn_diag_kernel<<<blocks, threads>>>(h, x, We1, be1, We2, be2, Wa, ba,
                                          Wn1, bn1, Wn2, bn2, out, xout, R);
}

// round 4
// speedup vs baseline: 1.2286x; 1.2286x over previous
#include <cuda_runtime.h>
#include <math.h>

// EGNN layer collapsed to the diagonal (eye-mask kills off-diagonal edges).
// Per row r: t1 = silu(h@(We1a+We1b) + sqrt(EPS)*We1[2F] + be1)
//            t2 = silu(t1@We2 + be2)
//            att = sigmoid(t2.Wa + ba)        [warp-uniform scalar]
//            t3 = silu(bn1 + h@Wn1a + att*(t2@Wn1b))   <- att factored out
//            out = t3@Wn2 + bn2
// Two rows per warp; lane = neuron. 128-thread blocks -> 256 blocks covers all
// 148 SMs. __launch_bounds__(128, 1) prevents ptxas from demoting the weight
// register arrays to local memory (the R3 regression: regs=32 + LDL traffic).

#define SQRT_EPS 0.0031622776601683794f  // sqrt(1e-5)
#define FULL 0xffffffffu

__device__ __forceinline__ float silu_f(float v) {
    return __fdividef(v, 1.0f + __expf(-v));
}
__device__ __forceinline__ float sigmoid_f(float v) {
    return __fdividef(1.0f, 1.0f + __expf(-v));
}

__global__ void __launch_bounds__(128, 1)
egnn_diag_kernel(const float* __restrict__ h,
                 const float* __restrict__ x,
                 const float* __restrict__ We1, const float* __restrict__ be1,
                 const float* __restrict__ We2, const float* __restrict__ be2,
                 const float* __restrict__ Wa,  const float* __restrict__ ba,
                 const float* __restrict__ Wn1, const float* __restrict__ bn1,
                 const float* __restrict__ Wn2, const float* __restrict__ bn2,
                 float* __restrict__ out, float* __restrict__ xout, int R)
{
    const int warp = (blockIdx.x * blockDim.x + threadIdx.x) >> 5;
    const int lane = threadIdx.x & 31;
    const int r0 = warp * 2;
    const int r1 = r0 + 1;
    if (r0 >= R) return;
    const bool has1 = (r1 < R);

    // ---- independent front-loaded work ----
    const float hv0 = h[r0 * 32 + lane];
    const float hv1 = has1 ? h[r1 * 32 + lane] : 0.f;

    if (lane < 3) {
        xout[r0 * 3 + lane] = x[r0 * 3 + lane];
        if (has1) xout[r1 * 3 + lane] = x[r1 * 3 + lane];
    }

    const float b1  = be1[lane] + SQRT_EPS * We1[64 * 32 + lane];
    const float b2  = be2[lane];
    const float wa  = Wa[lane];
    const float ba0 = ba[0];
    const float b3  = bn1[lane];
    const float b4  = bn2[lane];

    // critical-path weights into registers (loads overlap layer-1 compute)
    float we2r[32], wn2r[32];
    #pragma unroll
    for (int f = 0; f < 32; ++f) we2r[f] = We2[f * 32 + lane];
    #pragma unroll
    for (int f = 0; f < 32; ++f) wn2r[f] = Wn2[f * 32 + lane];

    // ---- layer 1 + S_h fused (reuse shfl(hv,f) for We1 and Wn1a) ----
    float a0_0 = b1, a1_0 = 0.f, a0_1 = b1, a1_1 = 0.f;
    float sh0a = 0.f, sh0b = 0.f, sh1a = 0.f, sh1b = 0.f;
    #pragma unroll
    for (int f = 0; f < 32; f += 2) {
        const float w1a = We1[(f + 0) * 32 + lane] + We1[(32 + f + 0) * 32 + lane];
        const float wna = Wn1[(f + 0) * 32 + lane];
        const float hf0a = __shfl_sync(FULL, hv0, f + 0);
        const float hf1a = __shfl_sync(FULL, hv1, f + 0);
        a0_0 += hf0a * w1a;  a0_1 += hf1a * w1a;
        sh0a += hf0a * wna;  sh1a += hf1a * wna;

        const float w1b = We1[(f + 1) * 32 + lane] + We1[(32 + f + 1) * 32 + lane];
        const float wnb = Wn1[(f + 1) * 32 + lane];
        const float hf0b = __shfl_sync(FULL, hv0, f + 1);
        const float hf1b = __shfl_sync(FULL, hv1, f + 1);
        a1_0 += hf0b * w1b;  a1_1 += hf1b * w1b;
        sh0b += hf0b * wnb;  sh1b += hf1b * wnb;
    }
    const float t1_0 = silu_f(a0_0 + a1_0);
    const float t1_1 = silu_f(a0_1 + a1_1);
    const float sh0 = sh0a + sh0b;
    const float sh1 = sh1a + sh1b;

    // ---- layer 2: t2 = silu(t1 @ We2 + be2), register weights ----
    a0_0 = b2; a1_0 = 0.f; a0_1 = b2; a1_1 = 0.f;
    #pragma unroll
    for (int f = 0; f < 32; f += 2) {
        a0_0 += __shfl_sync(FULL, t1_0, f + 0) * we2r[f + 0];
        a0_1 += __shfl_sync(FULL, t1_1, f + 0) * we2r[f + 0];
        a1_0 += __shfl_sync(FULL, t1_0, f + 1) * we2r[f + 1];
        a1_1 += __shfl_sync(FULL, t1_1, f + 1) * we2r[f + 1];
    }
    const float t2_0 = silu_f(a0_0 + a1_0);
    const float t2_1 = silu_f(a0_1 + a1_1);

    // ---- att reduction (butterfly) overlapped with S_t2 = t2 @ Wn1b ----
    float s0 = t2_0 * wa;
    float s1 = t2_1 * wa;
    float st0a = 0.f, st0b = 0.f, st1a = 0.f, st1b = 0.f;
    #pragma unroll
    for (int f = 0; f < 32; f += 2) {
        const float wba = Wn1[(32 + f + 0) * 32 + lane];
        const float wbb = Wn1[(32 + f + 1) * 32 + lane];
        st0a += __shfl_sync(FULL, t2_0, f + 0) * wba;
        st1a += __shfl_sync(FULL, t2_1, f + 0) * wba;
        st0b += __shfl_sync(FULL, t2_0, f + 1) * wbb;
        st1b += __shfl_sync(FULL, t2_1, f + 1) * wbb;
    }
    #pragma unroll
    for (int off = 16; off > 0; off >>= 1) {
        s0 += __shfl_xor_sync(FULL, s0, off);
        s1 += __shfl_xor_sync(FULL, s1, off);
    }
    const float att0 = sigmoid_f(s0 + ba0);
    const float att1 = sigmoid_f(s1 + ba0);

    // ---- layer 3 epilogue: t3 = silu(b3 + S_h + att * S_t2) ----
    const float t3_0 = silu_f(b3 + sh0 + att0 * (st0a + st0b));
    const float t3_1 = silu_f(b3 + sh1 + att1 * (st1a + st1b));

    // ---- layer 4: out = t3 @ Wn2 + bn2, register weights ----
    a0_0 = b4; a1_0 = 0.f; a0_1 = b4; a1_1 = 0.f;
    #pragma unroll
    for (int f = 0; f < 32; f += 2) {
        a0_0 += __shfl_sync(FULL, t3_0, f + 0) * wn2r[f + 0];
        a0_1 += __shfl_sync(FULL, t3_1, f + 0) * wn2r[f + 0];
        a1_0 += __shfl_sync(FULL, t3_0, f + 1) * wn2r[f + 1];
        a1_1 += __shfl_sync(FULL, t3_1, f + 1) * wn2r[f + 1];
    }

    out[r0 * 32 + lane] = a0_0 + a1_0;
    if (has1) out[r1 * 32 + lane] = a0_1 + a1_1;
}

extern "C" void kernel_launch(void* const* d_in, const int* in_sizes, int n_in,
                              void* d_out, int out_size)
{
    const float* h   = (const float*)d_in[0];
    const float* x   = (const float*)d_in[1];
    const float* We1 = (const float*)d_in[2];
    const float* be1 = (const float*)d_in[3];
    const float* We2 = (const float*)d_in[4];
    const float* be2 = (const float*)d_in[5];
    const float* Wa  = (const float*)d_in[6];
    const float* ba  = (const float*)d_in[7];
    const float* Wn1 = (const float*)d_in[8];
    const float* bn1 = (const float*)d_in[9];
    const float* Wn2 = (const float*)d_in[10];
    const float* bn2 = (const float*)d_in[11];

    const int R = in_sizes[0] / 32;          // B*N rows
    float* out  = (float*)d_out;             // [R, 32]
    float* xout = out + (size_t)R * 32;      // [R, 3] passthrough

    const int nwarps  = (R + 1) / 2;         // 2 rows per warp -> 1024 warps
    const int threads = 128;                 // 4 warps/block -> 256 blocks
    const int blocks  = (nwarps * 32 + threads - 1) / threads;
    egnn_diag_kernel<<<blocks, threads>>>(h, x, We1, be1, We2, be2, Wa, ba,
                                          Wn1, bn1, Wn2, bn2, out, xout, R);
}

// round 5
// speedup vs baseline: 1.2694x; 1.0332x over previous
#include <cuda_runtime.h>
#include <math.h>

// EGNN layer collapsed to the diagonal. Per row r:
//   t1 = silu(h@(We1a+We1b) + sqrt(EPS)*We1[2F] + be1)
//   t2 = silu(t1@We2 + be2)
//   att = sigmoid(t2.Wa + ba)                      [warp-uniform scalar]
//   t3 = silu(bn1 + h@Wn1a + att*(t2@Wn1b))        [att factored out]
//   out = t3@Wn2 + bn2
// Kernel is chip-wide ISSUE-SLOT bound (elapsed ~ total dyn instructions).
// 4 rows per warp: weight loads amortize 4x, 4 independent dep chains per
// accumulator class. 64-thread blocks -> 256 blocks cover all 148 SMs.

#define SQRT_EPS 0.0031622776601683794f  // sqrt(1e-5)
#define FULL 0xffffffffu

__device__ __forceinline__ float silu_f(float v) {
    return __fdividef(v, 1.0f + __expf(-v));
}
__device__ __forceinline__ float sigmoid_f(float v) {
    return __fdividef(1.0f, 1.0f + __expf(-v));
}

__global__ void __launch_bounds__(64, 1)
egnn_diag_kernel(const float* __restrict__ h,
                 const float* __restrict__ x,
                 const float* __restrict__ We1, const float* __restrict__ be1,
                 const float* __restrict__ We2, const float* __restrict__ be2,
                 const float* __restrict__ Wa,  const float* __restrict__ ba,
                 const float* __restrict__ Wn1, const float* __restrict__ bn1,
                 const float* __restrict__ Wn2, const float* __restrict__ bn2,
                 float* __restrict__ out, float* __restrict__ xout, int R)
{
    const int warp = (blockIdx.x * blockDim.x + threadIdx.x) >> 5;
    const int lane = threadIdx.x & 31;
    const int r0 = warp * 4;
    if (r0 >= R) return;

    // ---- independent front-loaded work ----
    float hv[4];
    #pragma unroll
    for (int k = 0; k < 4; ++k)
        hv[k] = (r0 + k < R) ? h[(r0 + k) * 32 + lane] : 0.f;

    // x passthrough: 12 consecutive floats per warp (rows r0..r0+3)
    if (lane < 12 && r0 * 3 + lane < R * 3)
        xout[r0 * 3 + lane] = x[r0 * 3 + lane];

    const float b1  = be1[lane] + SQRT_EPS * We1[64 * 32 + lane];
    const float b2  = be2[lane];
    const float wa  = Wa[lane];
    const float ba0 = ba[0];
    const float b3  = bn1[lane];
    const float b4  = bn2[lane];

    // critical-path weights into registers (loads overlap layer-1 compute)
    float we2r[32], wn2r[32];
    #pragma unroll
    for (int f = 0; f < 32; ++f) we2r[f] = We2[f * 32 + lane];
    #pragma unroll
    for (int f = 0; f < 32; ++f) wn2r[f] = Wn2[f * 32 + lane];

    // ---- layer 1 + S_h fused (reuse shfl(hv,f) for We1 and Wn1a) ----
    float acc[4], sh[4];
    #pragma unroll
    for (int k = 0; k < 4; ++k) { acc[k] = b1; sh[k] = 0.f; }
    #pragma unroll
    for (int f = 0; f < 32; ++f) {
        const float w1 = We1[f * 32 + lane] + We1[(32 + f) * 32 + lane];
        const float wn = Wn1[f * 32 + lane];
        #pragma unroll
        for (int k = 0; k < 4; ++k) {
            const float hf = __shfl_sync(FULL, hv[k], f);
            acc[k] += hf * w1;
            sh[k]  += hf * wn;
        }
    }
    float t1[4];
    #pragma unroll
    for (int k = 0; k < 4; ++k) t1[k] = silu_f(acc[k]);

    // ---- layer 2: t2 = silu(t1 @ We2 + be2), register weights ----
    #pragma unroll
    for (int k = 0; k < 4; ++k) acc[k] = b2;
    #pragma unroll
    for (int f = 0; f < 32; ++f) {
        const float wt = we2r[f];
        #pragma unroll
        for (int k = 0; k < 4; ++k)
            acc[k] += __shfl_sync(FULL, t1[k], f) * wt;
    }
    float t2[4];
    #pragma unroll
    for (int k = 0; k < 4; ++k) t2[k] = silu_f(acc[k]);

    // ---- att butterfly overlapped with S_t2 = t2 @ Wn1b ----
    float s[4], st[4];
    #pragma unroll
    for (int k = 0; k < 4; ++k) { s[k] = t2[k] * wa; st[k] = 0.f; }
    #pragma unroll
    for (int f = 0; f < 32; ++f) {
        const float wb = Wn1[(32 + f) * 32 + lane];
        #pragma unroll
        for (int k = 0; k < 4; ++k)
            st[k] += __shfl_sync(FULL, t2[k], f) * wb;
    }
    #pragma unroll
    for (int off = 16; off > 0; off >>= 1) {
        #pragma unroll
        for (int k = 0; k < 4; ++k)
            s[k] += __shfl_xor_sync(FULL, s[k], off);
    }

    // ---- layer 3 epilogue: t3 = silu(b3 + S_h + att * S_t2) ----
    float t3[4];
    #pragma unroll
    for (int k = 0; k < 4; ++k) {
        const float att = sigmoid_f(s[k] + ba0);
        t3[k] = silu_f(b3 + sh[k] + att * st[k]);
    }

    // ---- layer 4: out = t3 @ Wn2 + bn2, register weights ----
    #pragma unroll
    for (int k = 0; k < 4; ++k) acc[k] = b4;
    #pragma unroll
    for (int f = 0; f < 32; ++f) {
        const float wt = wn2r[f];
        #pragma unroll
        for (int k = 0; k < 4; ++k)
            acc[k] += __shfl_sync(FULL, t3[k], f) * wt;
    }

    #pragma unroll
    for (int k = 0; k < 4; ++k)
        if (r0 + k < R) out[(r0 + k) * 32 + lane] = acc[k];
}

extern "C" void kernel_launch(void* const* d_in, const int* in_sizes, int n_in,
                              void* d_out, int out_size)
{
    const float* h   = (const float*)d_in[0];
    const float* x   = (const float*)d_in[1];
    const float* We1 = (const float*)d_in[2];
    const float* be1 = (const float*)d_in[3];
    const float* We2 = (const float*)d_in[4];
    const float* be2 = (const float*)d_in[5];
    const float* Wa  = (const float*)d_in[6];
    const float* ba  = (const float*)d_in[7];
    const float* Wn1 = (const float*)d_in[8];
    const float* bn1 = (const float*)d_in[9];
    const float* Wn2 = (const float*)d_in[10];
    const float* bn2 = (const float*)d_in[11];

    const int R = in_sizes[0] / 32;          // B*N rows
    float* out  = (float*)d_out;             // [R, 32]
    float* xout = out + (size_t)R * 32;      // [R, 3] passthrough

    const int nwarps  = (R + 3) / 4;         // 4 rows per warp -> 512 warps
    const int threads = 64;                  // 2 warps/block -> 256 blocks
    const int blocks  = (nwarps * 32 + threads - 1) / threads;
    egnn_diag_kernel<<<blocks, threads>>>(h, x, We1, be1, We2, be2, Wa, ba,
                                          Wn1, bn1, Wn2, bn2, out, xout, R);
}